// round 11
// baseline (speedup 1.0000x reference)
#include <cuda_runtime.h>
#include <cuda_bf16.h>
#include <cstdint>

#define B_  1024
#define I_  256
#define N_  512
#define D_  6
#define U_  16
#define L_  64
#define ND_ (N_ * D_)   // 3072

__device__ float g_W  [I_ * ND_];            // sparsemax weights, [k=I][m=ND]
__device__ __nv_bfloat16 g_Wh[ND_ * I_];     // W transposed hi, [m][k]
__device__ __nv_bfloat16 g_Wl[ND_ * I_];     // W transposed lo, [m][k]
__device__ __nv_bfloat16 g_xh[B_ * I_];      // x hi, [j][k]
__device__ __nv_bfloat16 g_xl[B_ * I_];      // x lo, [j][k]
__device__ float g_sc [ND_];                 // 0.5*exp(-lt)
__device__ float g_of [ND_];                 // 0.5 - th*0.5*exp(-lt)
__device__ uint32_t g_respP[N_ * U_ * L_];   // resp, tf32 bits, pair-interleaved

// dynamic smem layout (bytes)
#define OFF_XH   0                            // [128][72] bf16 = 18432
#define OFF_XL   18432                        // 18432
#define OFF_WH   36864                        // [48][72] bf16 = 6912
#define OFF_WL   43776                        // 6912
#define OFF_FV   50688                        // [48][132] f32 = 25344
#define OFF_RESP 76032                        // [128][72] u32 = 36864
#define OFF_SC   112896                       // [48] f32
#define OFF_OF   113088                       // [48] f32
#define SMEM_TOTAL 113280

__device__ __forceinline__ uint32_t tf32r(float x) {
    uint32_t r; asm("cvt.rna.tf32.f32 %0, %1;" : "=r"(r) : "f"(x)); return r;
}

__device__ __forceinline__ void mma_tf32(float c[4], uint32_t a0, uint32_t a1,
                                         uint32_t a2, uint32_t a3,
                                         uint32_t b0, uint32_t b1) {
    asm volatile(
        "mma.sync.aligned.m16n8k8.row.col.f32.tf32.tf32.f32 "
        "{%0,%1,%2,%3}, {%4,%5,%6,%7}, {%8,%9}, {%0,%1,%2,%3};"
        : "+f"(c[0]), "+f"(c[1]), "+f"(c[2]), "+f"(c[3])
        : "r"(a0), "r"(a1), "r"(a2), "r"(a3), "r"(b0), "r"(b1));
}

__device__ __forceinline__ void mma_bf16(float c[4], uint32_t a0, uint32_t a1,
                                         uint32_t a2, uint32_t a3,
                                         uint32_t b0, uint32_t b1) {
    asm volatile(
        "mma.sync.aligned.m16n8k16.row.col.f32.bf16.bf16.f32 "
        "{%0,%1,%2,%3}, {%4,%5,%6,%7}, {%8,%9}, {%0,%1,%2,%3};"
        : "+f"(c[0]), "+f"(c[1]), "+f"(c[2]), "+f"(c[3])
        : "r"(a0), "r"(a1), "r"(a2), "r"(a3), "r"(b0), "r"(b1));
}

// ---------------------------------------------------------------------------
// Kernel P: fused prep (unchanged from R10). 512 x 256.
// ---------------------------------------------------------------------------
__global__ void k_prep(const float* __restrict__ fsl,
                       const float* __restrict__ x,
                       const float* __restrict__ th,
                       const float* __restrict__ lt,
                       const float* __restrict__ resp) {
    int gt = blockIdx.x * blockDim.x + threadIdx.x;

    {   // sparsemax for (i,n) = gt
        const float* z = fsl + (size_t)gt * D_;
        float z0 = z[0], z1 = z[1], z2 = z[2], z3 = z[3], z4 = z[4], z5 = z[5];
        float s0 = z0, s1 = z1, s2 = z2, s3 = z3, s4 = z4, s5 = z5;
#define CSWP(a, b) { float _mx = fmaxf(a, b); float _mn = fminf(a, b); a = _mx; b = _mn; }
        CSWP(s1, s2) CSWP(s4, s5) CSWP(s0, s2) CSWP(s3, s5)
        CSWP(s0, s1) CSWP(s3, s4) CSWP(s2, s5) CSWP(s0, s3)
        CSWP(s1, s4) CSWP(s2, s4) CSWP(s1, s3) CSWP(s2, s3)
#undef CSWP
        float cs = s0; int k = 1; float ts = cs;
        cs += s1; if (1.0f + 2.0f * s1 > cs) { k = 2; ts = cs; }
        cs += s2; if (1.0f + 3.0f * s2 > cs) { k = 3; ts = cs; }
        cs += s3; if (1.0f + 4.0f * s3 > cs) { k = 4; ts = cs; }
        cs += s4; if (1.0f + 5.0f * s4 > cs) { k = 5; ts = cs; }
        cs += s5; if (1.0f + 6.0f * s5 > cs) { k = 6; ts = cs; }
        float tau = (ts - 1.0f) / (float)k;

        float* w = g_W + (size_t)gt * D_;
        w[0] = fmaxf(z0 - tau, 0.0f);
        w[1] = fmaxf(z1 - tau, 0.0f);
        w[2] = fmaxf(z2 - tau, 0.0f);
        w[3] = fmaxf(z3 - tau, 0.0f);
        w[4] = fmaxf(z4 - tau, 0.0f);
        w[5] = fmaxf(z5 - tau, 0.0f);
    }

    {   // resp -> tf32, pair-interleaved: col'(c) = 8*(c>>3) + 2*(c&3) + ((c>>2)&1)
        float4 v = ((const float4*)resp)[gt];
        int fi  = gt * 4;
        int nu  = fi >> 6;
        int c4  = fi & 63;
        int s   = c4 >> 3;
        int sig = (c4 >> 2) & 1;
        uint32_t* dst = g_respP + (size_t)nu * 64 + 8 * s + sig;
        dst[0] = tf32r(v.x);
        dst[2] = tf32r(v.y);
        dst[4] = tf32r(v.z);
        dst[6] = tf32r(v.w);
    }

    if (gt < (B_ * I_) / 4) {   // x split
        float4 v = ((const float4*)x)[gt];
        float f[4] = { v.x, v.y, v.z, v.w };
        __nv_bfloat16 h[4], l[4];
#pragma unroll
        for (int i = 0; i < 4; i++) {
            h[i] = __float2bfloat16_rn(f[i]);
            l[i] = __float2bfloat16_rn(f[i] - __bfloat162float(h[i]));
        }
        __nv_bfloat162 h01(h[0], h[1]), h23(h[2], h[3]);
        __nv_bfloat162 l01(l[0], l[1]), l23(l[2], l[3]);
        uint2 uh = make_uint2(*reinterpret_cast<uint32_t*>(&h01),
                              *reinterpret_cast<uint32_t*>(&h23));
        uint2 ul = make_uint2(*reinterpret_cast<uint32_t*>(&l01),
                              *reinterpret_cast<uint32_t*>(&l23));
        *(uint2*)(g_xh + (size_t)gt * 4) = uh;
        *(uint2*)(g_xl + (size_t)gt * 4) = ul;
    }

    if (gt < ND_) {
        float s = 0.5f * expf(-lt[gt]);
        g_sc[gt] = s;
        g_of[gt] = 0.5f - th[gt] * s;
    }
}

// ---------------------------------------------------------------------------
// Kernel T: transpose + bf16 split of W (unchanged)
// ---------------------------------------------------------------------------
__global__ void k_wsplit() {
    __shared__ float s[32][33];
    int t  = threadIdx.x;
    int m0 = blockIdx.x * 32;
    int k0 = blockIdx.y * 32;
    int r  = t >> 5, c = t & 31;

#pragma unroll
    for (int i = 0; i < 4; i++)
        s[r + i * 8][c] = g_W[(size_t)(k0 + r + i * 8) * ND_ + m0 + c];
    __syncthreads();

#pragma unroll
    for (int i = 0; i < 4; i++) {
        int r2 = r + i * 8;
        float v = s[c][r2];
        __nv_bfloat16 hi = __float2bfloat16_rn(v);
        __nv_bfloat16 lo = __float2bfloat16_rn(v - __bfloat162float(hi));
        g_Wh[(size_t)(m0 + r2) * I_ + k0 + c] = hi;
        g_Wl[(size_t)(m0 + r2) * I_ + k0 + c] = lo;
    }
}

// ---------------------------------------------------------------------------
// Kernel F (FUSED gemm + forest): block = (n-group of 8 -> 48 m) x (128 b).
// Phase 1: warps 0-5 compute FV[48][128] via bf16-split mma (K=256).
// Phase 2: all 8 warps run tf32 forest contraction from smem.
// Grid (8 b-tiles, 64 n-groups) = 512 blocks, 256 threads, 110.6KB dyn smem.
// ---------------------------------------------------------------------------
__global__ void __launch_bounds__(256) k_fused(float* __restrict__ out) {
    extern __shared__ char smem[];
    __nv_bfloat16* Xh_s = (__nv_bfloat16*)(smem + OFF_XH);   // [128][72]
    __nv_bfloat16* Xl_s = (__nv_bfloat16*)(smem + OFF_XL);
    __nv_bfloat16* Wh_s = (__nv_bfloat16*)(smem + OFF_WH);   // [48][72]
    __nv_bfloat16* Wl_s = (__nv_bfloat16*)(smem + OFF_WL);
    float*     FV_s   = (float*)(smem + OFF_FV);             // [48][132]
    uint32_t*  resp_s = (uint32_t*)(smem + OFF_RESP);        // [128][72]
    float*     sc_s   = (float*)(smem + OFF_SC);
    float*     of_s   = (float*)(smem + OFF_OF);

    int t    = threadIdx.x;
    int w    = t >> 5;
    int lane = t & 31;
    int g    = lane >> 2;
    int tig  = lane & 3;
    int bt   = blockIdx.x;   // 8 b-tiles of 128
    int ng   = blockIdx.y;   // 64 n-groups of 8 (48 m-rows)

    // ---- stage resp (tf32, pair-interleaved) + sc/of ----
    if (t < 48) { sc_s[t] = g_sc[ng * 48 + t]; of_s[t] = g_of[ng * 48 + t]; }
    {
        const uint4* src = (const uint4*)(g_respP + (size_t)ng * 8 * (U_ * L_));
#pragma unroll
        for (int j = 0; j < 8; j++) {
            int idx = t + j * 256;            // uint4 index in [0,2048)
            uint4 v = src[idx];
            int fi = idx * 4;
            int row = fi >> 6, col = fi & 63;
            *(uint4*)&resp_s[row * 72 + col] = v;
        }
    }

    // ---- phase 1: GEMM, warps 0-5 (M=48 -> 3 m-frags x 2 j-halves) ----
    int mf = w % 3, jh = w / 3;   // only meaningful for w < 6
    float acc[8][4];
#pragma unroll
    for (int jf = 0; jf < 8; jf++)
#pragma unroll
        for (int i = 0; i < 4; i++) acc[jf][i] = 0.0f;

    for (int kc = 0; kc < I_; kc += 64) {
        __syncthreads();   // previous chunk's readers done (also covers resp staging)
        {   // stage W chunk: 48 rows x 8 segs = 384 uint4 per matrix
#pragma unroll
            for (int i = 0; i < 2; i++) {
                int idx = t + i * 256;
                if (idx < 384) {
                    int row = idx >> 3, seg = idx & 7;
                    size_t go = (size_t)(ng * 48 + row) * I_ + kc + seg * 8;
                    *(uint4*)&Wh_s[row * 72 + seg * 8] = *(const uint4*)(g_Wh + go);
                    *(uint4*)&Wl_s[row * 72 + seg * 8] = *(const uint4*)(g_Wl + go);
                }
            }
            // stage X chunk: 128 rows x 8 segs = 1024 uint4 per matrix
#pragma unroll
            for (int i = 0; i < 4; i++) {
                int idx = t + i * 256;
                int row = idx >> 3, seg = idx & 7;
                size_t go = (size_t)(bt * 128 + row) * I_ + kc + seg * 8;
                *(uint4*)&Xh_s[row * 72 + seg * 8] = *(const uint4*)(g_xh + go);
                *(uint4*)&Xl_s[row * 72 + seg * 8] = *(const uint4*)(g_xl + go);
            }
        }
        __syncthreads();

        if (w < 6) {
#pragma unroll
            for (int kst = 0; kst < 4; kst++) {
                int k0 = kst * 16 + 2 * tig;
                int r0 = (mf * 16 + g) * 72, r1 = (mf * 16 + g + 8) * 72;
                uint32_t ah0 = *(uint32_t*)&Wh_s[r0 + k0];
                uint32_t ah1 = *(uint32_t*)&Wh_s[r1 + k0];
                uint32_t ah2 = *(uint32_t*)&Wh_s[r0 + k0 + 8];
                uint32_t ah3 = *(uint32_t*)&Wh_s[r1 + k0 + 8];
                uint32_t al0 = *(uint32_t*)&Wl_s[r0 + k0];
                uint32_t al1 = *(uint32_t*)&Wl_s[r1 + k0];
                uint32_t al2 = *(uint32_t*)&Wl_s[r0 + k0 + 8];
                uint32_t al3 = *(uint32_t*)&Wl_s[r1 + k0 + 8];

#pragma unroll
                for (int jf = 0; jf < 8; jf++) {
                    int xr = (jh * 64 + jf * 8 + g) * 72;
                    uint32_t bh0 = *(uint32_t*)&Xh_s[xr + k0];
                    uint32_t bh1 = *(uint32_t*)&Xh_s[xr + k0 + 8];
                    uint32_t bl0 = *(uint32_t*)&Xl_s[xr + k0];
                    uint32_t bl1 = *(uint32_t*)&Xl_s[xr + k0 + 8];
                    mma_bf16(acc[jf], ah0, ah1, ah2, ah3, bh0, bh1);
                    mma_bf16(acc[jf], al0, al1, al2, al3, bh0, bh1);
                    mma_bf16(acc[jf], ah0, ah1, ah2, ah3, bl0, bl1);
                }
            }
        }
    }

    // write FV fragments to smem
    if (w < 6) {
#pragma unroll
        for (int jf = 0; jf < 8; jf++) {
            int j  = jh * 64 + jf * 8 + 2 * tig;
            int r0 = (mf * 16 + g) * 132, r1 = (mf * 16 + g + 8) * 132;
            *(float2*)&FV_s[r0 + j] = make_float2(acc[jf][0], acc[jf][1]);
            *(float2*)&FV_s[r1 + j] = make_float2(acc[jf][2], acc[jf][3]);
        }
    }
    __syncthreads();

    // ---- phase 2: forest (all 8 warps; 16 b-rows per warp) ----
    float facc[2][4] = {};
    int b_loc = w * 16 + g;                 // local b rows b_loc, b_loc+8
    int b_r0  = bt * 128 + b_loc;

#pragma unroll
    for (int nl = 0; nl < 8; nl++) {
        float h0[6], h1[6];
#pragma unroll
        for (int d = 0; d < 6; d++) {
            float sc = sc_s[nl * 6 + d], of = of_s[nl * 6 + d];
            int fr = (nl * 6 + d) * 132;
            float v0 = FV_s[fr + b_loc]     * sc + of;
            float v1 = FV_s[fr + b_loc + 8] * sc + of;
            h0[d] = fminf(fmaxf(v0, 0.0f), 1.0f);
            h1[d] = fminf(fmaxf(v1, 0.0f), 1.0f);
        }

        float f0a = (tig & 1) ? (1.0f - h0[0]) : h0[0];
        float f0b = (tig & 1) ? (1.0f - h1[0]) : h1[0];
        float f1a = (tig & 2) ? (1.0f - h0[1]) : h0[1];
        float f1b = (tig & 2) ? (1.0f - h1[1]) : h1[1];
        float F0 = f0a * f1a, F1 = f0b * f1b;
        float A00 = F0 * h0[2], A01 = F0 * (1.0f - h0[2]);
        float A10 = F1 * h1[2], A11 = F1 * (1.0f - h1[2]);

        float S0[8], S1[8];
        {
            float p0 = h0[3], p1 = 1.0f - h0[3];
            float r0 = h0[4], r1 = 1.0f - h0[4];
            float q0 = p0 * r0, q1 = p1 * r0, q2 = p0 * r1, q3 = p1 * r1;
            float t5 = h0[5], u5 = 1.0f - h0[5];
            S0[0] = q0 * t5; S0[1] = q1 * t5; S0[2] = q2 * t5; S0[3] = q3 * t5;
            S0[4] = q0 * u5; S0[5] = q1 * u5; S0[6] = q2 * u5; S0[7] = q3 * u5;
        }
        {
            float p0 = h1[3], p1 = 1.0f - h1[3];
            float r0 = h1[4], r1 = 1.0f - h1[4];
            float q0 = p0 * r0, q1 = p1 * r0, q2 = p0 * r1, q3 = p1 * r1;
            float t5 = h1[5], u5 = 1.0f - h1[5];
            S1[0] = q0 * t5; S1[1] = q1 * t5; S1[2] = q2 * t5; S1[3] = q3 * t5;
            S1[4] = q0 * u5; S1[5] = q1 * u5; S1[6] = q2 * u5; S1[7] = q3 * u5;
        }

#pragma unroll
        for (int s = 0; s < 8; s++) {
            uint32_t a0 = __float_as_uint(A00 * S0[s]);
            uint32_t a1 = __float_as_uint(A10 * S1[s]);
            uint32_t a2 = __float_as_uint(A01 * S0[s]);
            uint32_t a3 = __float_as_uint(A11 * S1[s]);
#pragma unroll
            for (int nr = 0; nr < 2; nr++) {
                uint2 bb = *(const uint2*)&resp_s[(nl * 16 + nr * 8 + g) * 72 + 8 * s + 2 * tig];
                mma_tf32(facc[nr], a0, a1, a2, a3, bb.x, bb.y);
            }
        }
    }

#pragma unroll
    for (int nr = 0; nr < 2; nr++) {
        int u = nr * 8 + 2 * tig;
        atomicAdd(&out[b_r0 * U_ + u],           facc[nr][0]);
        atomicAdd(&out[b_r0 * U_ + u + 1],       facc[nr][1]);
        atomicAdd(&out[(b_r0 + 8) * U_ + u],     facc[nr][2]);
        atomicAdd(&out[(b_r0 + 8) * U_ + u + 1], facc[nr][3]);
    }
}

// ---------------------------------------------------------------------------
extern "C" void kernel_launch(void* const* d_in, const int* in_sizes, int n_in,
                              void* d_out, int out_size) {
    const float* x    = (const float*)d_in[0];  // [B, I]
    const float* fsl  = (const float*)d_in[1];  // [I, N, D]
    const float* th   = (const float*)d_in[2];  // [N, D]
    const float* lt   = (const float*)d_in[3];  // [N, D]
    const float* resp = (const float*)d_in[4];  // [N, U, 2^D]
    float* out = (float*)d_out;                 // [B, U]

    cudaFuncSetAttribute(k_fused, cudaFuncAttributeMaxDynamicSharedMemorySize,
                         SMEM_TOTAL);

    cudaMemsetAsync(out, 0, (size_t)B_ * U_ * sizeof(float), 0);

    k_prep<<<512, 256>>>(fsl, x, th, lt, resp);
    k_wsplit<<<dim3(ND_ / 32, I_ / 32), 256>>>();
    k_fused<<<dim3(B_ / 128, N_ / 8), 256, SMEM_TOTAL>>>(out);
}

// round 12
// speedup vs baseline: 1.0461x; 1.0461x over previous
#include <cuda_runtime.h>
#include <cuda_bf16.h>
#include <cstdint>

#define B_  1024
#define I_  256
#define N_  512
#define D_  6
#define U_  16
#define L_  64
#define ND_ (N_ * D_)   // 3072

__device__ float g_W  [I_ * ND_];            // sparsemax weights, [k=I][m=ND]
__device__ __nv_bfloat16 g_Wh[ND_ * I_];     // W transposed hi, [m][k]
__device__ __nv_bfloat16 g_Wl[ND_ * I_];     // W transposed lo, [m][k]
__device__ __nv_bfloat16 g_xh[B_ * I_];      // x hi, [j][k]
__device__ __nv_bfloat16 g_xl[B_ * I_];      // x lo, [j][k]
__device__ float g_FVt[ND_ * B_];            // feature values transposed, [m][j]
__device__ float g_sc [ND_];                 // 0.5*exp(-lt)
__device__ float g_of [ND_];                 // 0.5 - th*0.5*exp(-lt)
__device__ uint32_t g_respP[N_ * U_ * L_];   // resp, tf32 bits, pair-interleaved

__device__ __forceinline__ uint32_t tf32r(float x) {
    uint32_t r; asm("cvt.rna.tf32.f32 %0, %1;" : "=r"(r) : "f"(x)); return r;
}

__device__ __forceinline__ void mma_tf32(float c[4], uint32_t a0, uint32_t a1,
                                         uint32_t a2, uint32_t a3,
                                         uint32_t b0, uint32_t b1) {
    asm volatile(
        "mma.sync.aligned.m16n8k8.row.col.f32.tf32.tf32.f32 "
        "{%0,%1,%2,%3}, {%4,%5,%6,%7}, {%8,%9}, {%0,%1,%2,%3};"
        : "+f"(c[0]), "+f"(c[1]), "+f"(c[2]), "+f"(c[3])
        : "r"(a0), "r"(a1), "r"(a2), "r"(a3), "r"(b0), "r"(b1));
}

__device__ __forceinline__ void mma_bf16(float c[4], uint32_t a0, uint32_t a1,
                                         uint32_t a2, uint32_t a3,
                                         uint32_t b0, uint32_t b1) {
    asm volatile(
        "mma.sync.aligned.m16n8k16.row.col.f32.bf16.bf16.f32 "
        "{%0,%1,%2,%3}, {%4,%5,%6,%7}, {%8,%9}, {%0,%1,%2,%3};"
        : "+f"(c[0]), "+f"(c[1]), "+f"(c[2]), "+f"(c[3])
        : "r"(a0), "r"(a1), "r"(a2), "r"(a3), "r"(b0), "r"(b1));
}

// ---------------------------------------------------------------------------
// Kernel P: fused prep. 512 x 256. Sparsemax z via 3x LDG.64.
// ---------------------------------------------------------------------------
__global__ void k_prep(const float* __restrict__ fsl,
                       const float* __restrict__ x,
                       const float* __restrict__ th,
                       const float* __restrict__ lt,
                       const float* __restrict__ resp) {
    int gt = blockIdx.x * blockDim.x + threadIdx.x;

    {   // sparsemax for (i,n) = gt ; z loads as 3 x float2 (8B aligned)
        const float2* z2 = (const float2*)(fsl + (size_t)gt * D_);
        float2 za = z2[0], zb = z2[1], zc = z2[2];
        float z0 = za.x, z1 = za.y, z2v = zb.x, z3 = zb.y, z4 = zc.x, z5 = zc.y;
        float s0 = z0, s1 = z1, s2 = z2v, s3 = z3, s4 = z4, s5 = z5;
#define CSWP(a, b) { float _mx = fmaxf(a, b); float _mn = fminf(a, b); a = _mx; b = _mn; }
        CSWP(s1, s2) CSWP(s4, s5) CSWP(s0, s2) CSWP(s3, s5)
        CSWP(s0, s1) CSWP(s3, s4) CSWP(s2, s5) CSWP(s0, s3)
        CSWP(s1, s4) CSWP(s2, s4) CSWP(s1, s3) CSWP(s2, s3)
#undef CSWP
        float cs = s0; int k = 1; float ts = cs;
        cs += s1; if (1.0f + 2.0f * s1 > cs) { k = 2; ts = cs; }
        cs += s2; if (1.0f + 3.0f * s2 > cs) { k = 3; ts = cs; }
        cs += s3; if (1.0f + 4.0f * s3 > cs) { k = 4; ts = cs; }
        cs += s4; if (1.0f + 5.0f * s4 > cs) { k = 5; ts = cs; }
        cs += s5; if (1.0f + 6.0f * s5 > cs) { k = 6; ts = cs; }
        float tau = (ts - 1.0f) / (float)k;

        float* w = g_W + (size_t)gt * D_;
        float2* w2 = (float2*)w;
        w2[0] = make_float2(fmaxf(z0 - tau, 0.0f), fmaxf(z1 - tau, 0.0f));
        w2[1] = make_float2(fmaxf(z2v - tau, 0.0f), fmaxf(z3 - tau, 0.0f));
        w2[2] = make_float2(fmaxf(z4 - tau, 0.0f), fmaxf(z5 - tau, 0.0f));
    }

    {   // resp -> tf32, pair-interleaved: col'(c) = 8*(c>>3) + 2*(c&3) + ((c>>2)&1)
        float4 v = ((const float4*)resp)[gt];
        int fi  = gt * 4;
        int nu  = fi >> 6;
        int c4  = fi & 63;
        int s   = c4 >> 3;
        int sig = (c4 >> 2) & 1;
        uint32_t* dst = g_respP + (size_t)nu * 64 + 8 * s + sig;
        dst[0] = tf32r(v.x);
        dst[2] = tf32r(v.y);
        dst[4] = tf32r(v.z);
        dst[6] = tf32r(v.w);
    }

    if (gt < (B_ * I_) / 4) {   // x split
        float4 v = ((const float4*)x)[gt];
        float f[4] = { v.x, v.y, v.z, v.w };
        __nv_bfloat16 h[4], l[4];
#pragma unroll
        for (int i = 0; i < 4; i++) {
            h[i] = __float2bfloat16_rn(f[i]);
            l[i] = __float2bfloat16_rn(f[i] - __bfloat162float(h[i]));
        }
        __nv_bfloat162 h01(h[0], h[1]), h23(h[2], h[3]);
        __nv_bfloat162 l01(l[0], l[1]), l23(l[2], l[3]);
        uint2 uh = make_uint2(*reinterpret_cast<uint32_t*>(&h01),
                              *reinterpret_cast<uint32_t*>(&h23));
        uint2 ul = make_uint2(*reinterpret_cast<uint32_t*>(&l01),
                              *reinterpret_cast<uint32_t*>(&l23));
        *(uint2*)(g_xh + (size_t)gt * 4) = uh;
        *(uint2*)(g_xl + (size_t)gt * 4) = ul;
    }

    if (gt < ND_) {
        float s = 0.5f * expf(-lt[gt]);
        g_sc[gt] = s;
        g_of[gt] = 0.5f - th[gt] * s;
    }
}

// ---------------------------------------------------------------------------
// Kernel T: transpose + bf16 split of W (unchanged)
// ---------------------------------------------------------------------------
__global__ void k_wsplit() {
    __shared__ float s[32][33];
    int t  = threadIdx.x;
    int m0 = blockIdx.x * 32;
    int k0 = blockIdx.y * 32;
    int r  = t >> 5, c = t & 31;

#pragma unroll
    for (int i = 0; i < 4; i++)
        s[r + i * 8][c] = g_W[(size_t)(k0 + r + i * 8) * ND_ + m0 + c];
    __syncthreads();

#pragma unroll
    for (int i = 0; i < 4; i++) {
        int r2 = r + i * 8;
        float v = s[c][r2];
        __nv_bfloat16 hi = __float2bfloat16_rn(v);
        __nv_bfloat16 lo = __float2bfloat16_rn(v - __bfloat162float(hi));
        g_Wh[(size_t)(m0 + r2) * I_ + k0 + c] = hi;
        g_Wl[(size_t)(m0 + r2) * I_ + k0 + c] = lo;
    }
}

// ---------------------------------------------------------------------------
// Kernel B: tensor GEMM (unchanged from R10)
// ---------------------------------------------------------------------------
__global__ void __launch_bounds__(256) k_gemm() {
    __shared__ __nv_bfloat16 Wh_s[128][72], Wl_s[128][72];
    __shared__ __nv_bfloat16 Xh_s[64][72],  Xl_s[64][72];

    int t    = threadIdx.x;
    int w    = t >> 5;
    int lane = t & 31;
    int g    = lane >> 2;
    int tig  = lane & 3;
    int jt   = blockIdx.x;
    int mt   = blockIdx.y;

    float acc[8][4];
#pragma unroll
    for (int jf = 0; jf < 8; jf++)
#pragma unroll
        for (int i = 0; i < 4; i++) acc[jf][i] = 0.0f;

    for (int kc = 0; kc < I_; kc += 64) {
        __syncthreads();
        {
#pragma unroll
            for (int i = 0; i < 4; i++) {
                int idx = t + i * 256;
                int row = idx >> 3, seg = idx & 7;
                size_t go = (size_t)(mt * 128 + row) * I_ + kc + seg * 8;
                *(uint4*)&Wh_s[row][seg * 8] = *(const uint4*)(g_Wh + go);
                *(uint4*)&Wl_s[row][seg * 8] = *(const uint4*)(g_Wl + go);
            }
#pragma unroll
            for (int i = 0; i < 2; i++) {
                int idx = t + i * 256;
                int row = idx >> 3, seg = idx & 7;
                size_t go = (size_t)(jt * 64 + row) * I_ + kc + seg * 8;
                *(uint4*)&Xh_s[row][seg * 8] = *(const uint4*)(g_xh + go);
                *(uint4*)&Xl_s[row][seg * 8] = *(const uint4*)(g_xl + go);
            }
        }
        __syncthreads();

#pragma unroll
        for (int kst = 0; kst < 4; kst++) {
            int k0 = kst * 16 + 2 * tig;
            uint32_t ah0 = *(uint32_t*)&Wh_s[w * 16 + g][k0];
            uint32_t ah1 = *(uint32_t*)&Wh_s[w * 16 + g + 8][k0];
            uint32_t ah2 = *(uint32_t*)&Wh_s[w * 16 + g][k0 + 8];
            uint32_t ah3 = *(uint32_t*)&Wh_s[w * 16 + g + 8][k0 + 8];
            uint32_t al0 = *(uint32_t*)&Wl_s[w * 16 + g][k0];
            uint32_t al1 = *(uint32_t*)&Wl_s[w * 16 + g + 8][k0];
            uint32_t al2 = *(uint32_t*)&Wl_s[w * 16 + g][k0 + 8];
            uint32_t al3 = *(uint32_t*)&Wl_s[w * 16 + g + 8][k0 + 8];

#pragma unroll
            for (int jf = 0; jf < 8; jf++) {
                uint32_t bh0 = *(uint32_t*)&Xh_s[jf * 8 + g][k0];
                uint32_t bh1 = *(uint32_t*)&Xh_s[jf * 8 + g][k0 + 8];
                uint32_t bl0 = *(uint32_t*)&Xl_s[jf * 8 + g][k0];
                uint32_t bl1 = *(uint32_t*)&Xl_s[jf * 8 + g][k0 + 8];
                mma_bf16(acc[jf], ah0, ah1, ah2, ah3, bh0, bh1);
                mma_bf16(acc[jf], al0, al1, al2, al3, bh0, bh1);
                mma_bf16(acc[jf], ah0, ah1, ah2, ah3, bl0, bl1);
            }
        }
    }

    int m0 = mt * 128 + w * 16;
#pragma unroll
    for (int jf = 0; jf < 8; jf++) {
        int j = jt * 64 + jf * 8 + 2 * tig;
        *(float2*)&g_FVt[(size_t)(m0 + g) * B_ + j]     = make_float2(acc[jf][0], acc[jf][1]);
        *(float2*)&g_FVt[(size_t)(m0 + g + 8) * B_ + j] = make_float2(acc[jf][2], acc[jf][3]);
    }
}

// ---------------------------------------------------------------------------
// Kernel C (tensor forest): R10 structure + software-pipelined FVt loads.
// 256 threads, 128 b-rows x 8 n per block; grid (8, 64) = 512 blocks.
// ---------------------------------------------------------------------------
__global__ void __launch_bounds__(256) k_forest(float* __restrict__ out) {
    __shared__ uint32_t resp_s[8][U_][72];   // tf32 bits, pair-interleaved, padded
    __shared__ float sc_s[48], of_s[48];

    int t    = threadIdx.x;
    int w    = t >> 5;
    int lane = t & 31;
    int g    = lane >> 2;
    int tig  = lane & 3;
    int bt   = blockIdx.x;   // 8 b-tiles of 128
    int ng   = blockIdx.y;   // 64 n-groups of 8

    if (t < 48) { sc_s[t] = g_sc[ng * 48 + t]; of_s[t] = g_of[ng * 48 + t]; }

    {   // stage 8 response tiles: 8192 words, pure uint4 copy
        const uint4* src = (const uint4*)(g_respP + (size_t)ng * 8 * (U_ * L_));
#pragma unroll
        for (int j = 0; j < 8; j++) {
            int idx = t + j * 256;
            uint4 v = src[idx];
            int fi = idx * 4;
            int row = fi >> 6, col = fi & 63;
            *(uint4*)&resp_s[row >> 4][row & 15][col] = v;
        }
    }

    float acc[2][4] = {};
    int b_r0 = bt * 128 + w * 16 + g;    // rows b_r0, b_r0+8
    const float* fvb = g_FVt + (size_t)ng * 48 * B_;

    // prologue: prefetch nl=0's 12 FVt values
    float fv[2][12];
#pragma unroll
    for (int d = 0; d < 6; d++) {
        fv[0][d]     = fvb[(size_t)d * B_ + b_r0];
        fv[0][6 + d] = fvb[(size_t)d * B_ + b_r0 + 8];
    }

    __syncthreads();

#pragma unroll
    for (int nl = 0; nl < 8; nl++) {
        int cur = nl & 1, nxt = cur ^ 1;

        // prefetch next iteration's FVt while this one computes
        if (nl < 7) {
            const float* fvn = fvb + (size_t)(nl + 1) * 6 * B_;
#pragma unroll
            for (int d = 0; d < 6; d++) {
                fv[nxt][d]     = fvn[(size_t)d * B_ + b_r0];
                fv[nxt][6 + d] = fvn[(size_t)d * B_ + b_r0 + 8];
            }
        }

        float h0[6], h1[6];
#pragma unroll
        for (int d = 0; d < 6; d++) {
            float sc = sc_s[nl * 6 + d], of = of_s[nl * 6 + d];
            h0[d] = fminf(fmaxf(fv[cur][d]     * sc + of, 0.0f), 1.0f);
            h1[d] = fminf(fmaxf(fv[cur][6 + d] * sc + of, 0.0f), 1.0f);
        }

        float f0a = (tig & 1) ? (1.0f - h0[0]) : h0[0];
        float f0b = (tig & 1) ? (1.0f - h1[0]) : h1[0];
        float f1a = (tig & 2) ? (1.0f - h0[1]) : h0[1];
        float f1b = (tig & 2) ? (1.0f - h1[1]) : h1[1];
        float F0 = f0a * f1a, F1 = f0b * f1b;
        float A00 = F0 * h0[2], A01 = F0 * (1.0f - h0[2]);
        float A10 = F1 * h1[2], A11 = F1 * (1.0f - h1[2]);

        float S0[8], S1[8];
        {
            float p0 = h0[3], p1 = 1.0f - h0[3];
            float r0 = h0[4], r1 = 1.0f - h0[4];
            float q0 = p0 * r0, q1 = p1 * r0, q2 = p0 * r1, q3 = p1 * r1;
            float t5 = h0[5], u5 = 1.0f - h0[5];
            S0[0] = q0 * t5; S0[1] = q1 * t5; S0[2] = q2 * t5; S0[3] = q3 * t5;
            S0[4] = q0 * u5; S0[5] = q1 * u5; S0[6] = q2 * u5; S0[7] = q3 * u5;
        }
        {
            float p0 = h1[3], p1 = 1.0f - h1[3];
            float r0 = h1[4], r1 = 1.0f - h1[4];
            float q0 = p0 * r0, q1 = p1 * r0, q2 = p0 * r1, q3 = p1 * r1;
            float t5 = h1[5], u5 = 1.0f - h1[5];
            S1[0] = q0 * t5; S1[1] = q1 * t5; S1[2] = q2 * t5; S1[3] = q3 * t5;
            S1[4] = q0 * u5; S1[5] = q1 * u5; S1[6] = q2 * u5; S1[7] = q3 * u5;
        }

#pragma unroll
        for (int s = 0; s < 8; s++) {
            uint32_t a0 = __float_as_uint(A00 * S0[s]);
            uint32_t a1 = __float_as_uint(A10 * S1[s]);
            uint32_t a2 = __float_as_uint(A01 * S0[s]);
            uint32_t a3 = __float_as_uint(A11 * S1[s]);
#pragma unroll
            for (int nr = 0; nr < 2; nr++) {
                uint2 bb = *(const uint2*)&resp_s[nl][nr * 8 + g][8 * s + 2 * tig];
                mma_tf32(acc[nr], a0, a1, a2, a3, bb.x, bb.y);
            }
        }
    }

#pragma unroll
    for (int nr = 0; nr < 2; nr++) {
        int u = nr * 8 + 2 * tig;
        atomicAdd(&out[b_r0 * U_ + u],           acc[nr][0]);
        atomicAdd(&out[b_r0 * U_ + u + 1],       acc[nr][1]);
        atomicAdd(&out[(b_r0 + 8) * U_ + u],     acc[nr][2]);
        atomicAdd(&out[(b_r0 + 8) * U_ + u + 1], acc[nr][3]);
    }
}

// ---------------------------------------------------------------------------
extern "C" void kernel_launch(void* const* d_in, const int* in_sizes, int n_in,
                              void* d_out, int out_size) {
    const float* x    = (const float*)d_in[0];  // [B, I]
    const float* fsl  = (const float*)d_in[1];  // [I, N, D]
    const float* th   = (const float*)d_in[2];  // [N, D]
    const float* lt   = (const float*)d_in[3];  // [N, D]
    const float* resp = (const float*)d_in[4];  // [N, U, 2^D]
    float* out = (float*)d_out;                 // [B, U]

    cudaMemsetAsync(out, 0, (size_t)B_ * U_ * sizeof(float), 0);

    k_prep<<<512, 256>>>(fsl, x, th, lt, resp);
    k_wsplit<<<dim3(ND_ / 32, I_ / 32), 256>>>();
    k_gemm<<<dim3(B_ / 64, ND_ / 128), 256>>>();
    k_forest<<<dim3(B_ / 128, N_ / 8), 256>>>(out);
}

// round 13
// speedup vs baseline: 1.1625x; 1.1113x over previous
#include <cuda_runtime.h>
#include <cuda_bf16.h>
#include <cstdint>

#define B_  1024
#define I_  256
#define N_  512
#define D_  6
#define U_  16
#define L_  64
#define ND_ (N_ * D_)   // 3072

__device__ __nv_bfloat16 g_Wh[ND_ * I_];     // W transposed hi, [m][k]
__device__ __nv_bfloat16 g_Wl[ND_ * I_];     // W transposed lo, [m][k]
__device__ __nv_bfloat16 g_xh[B_ * I_];      // x hi, [j][k]
__device__ __nv_bfloat16 g_xl[B_ * I_];      // x lo, [j][k]
__device__ float g_FVt[ND_ * B_];            // feature values transposed, [m][j]
__device__ float g_sc [ND_];                 // 0.5*exp(-lt)
__device__ float g_of [ND_];                 // 0.5 - th*0.5*exp(-lt)
__device__ uint32_t g_respP[N_ * U_ * L_];   // resp, tf32 bits, pair-interleaved

__device__ __forceinline__ uint32_t tf32r(float x) {
    uint32_t r; asm("cvt.rna.tf32.f32 %0, %1;" : "=r"(r) : "f"(x)); return r;
}

__device__ __forceinline__ void mma_tf32(float c[4], uint32_t a0, uint32_t a1,
                                         uint32_t a2, uint32_t a3,
                                         uint32_t b0, uint32_t b1) {
    asm volatile(
        "mma.sync.aligned.m16n8k8.row.col.f32.tf32.tf32.f32 "
        "{%0,%1,%2,%3}, {%4,%5,%6,%7}, {%8,%9}, {%0,%1,%2,%3};"
        : "+f"(c[0]), "+f"(c[1]), "+f"(c[2]), "+f"(c[3])
        : "r"(a0), "r"(a1), "r"(a2), "r"(a3), "r"(b0), "r"(b1));
}

__device__ __forceinline__ void mma_bf16(float c[4], uint32_t a0, uint32_t a1,
                                         uint32_t a2, uint32_t a3,
                                         uint32_t b0, uint32_t b1) {
    asm volatile(
        "mma.sync.aligned.m16n8k16.row.col.f32.bf16.bf16.f32 "
        "{%0,%1,%2,%3}, {%4,%5,%6,%7}, {%8,%9}, {%0,%1,%2,%3};"
        : "+f"(c[0]), "+f"(c[1]), "+f"(c[2]), "+f"(c[3])
        : "r"(a0), "r"(a1), "r"(a2), "r"(a3), "r"(b0), "r"(b1));
}

// ---------------------------------------------------------------------------
// Kernel P: fused prep. 512 blocks x 256 threads.
//   sparsemax for a 32i x 8n patch -> smem transpose -> bf16 hi/lo W output
//   resp -> tf32 pair-interleaved (gather form: 2x LDG.64 -> 1x STG.128)
//   x bf16 hi/lo split; sc/of
// ---------------------------------------------------------------------------
__global__ void __launch_bounds__(256) k_prep(const float* __restrict__ fsl,
                                              const float* __restrict__ x,
                                              const float* __restrict__ th,
                                              const float* __restrict__ lt,
                                              const float* __restrict__ resp) {
    __shared__ float fsm[48][33];   // [m_local][i_local]

    int t   = threadIdx.x;
    int bid = blockIdx.x;
    int gt  = bid * 256 + t;

    // ---- sparsemax for (i, n) = (it*32+li, nt*8+ln) ----
    int it = bid >> 6;       // 0..7
    int nt = bid & 63;       // 0..63
    int li = t >> 3, ln = t & 7;
    {
        const float2* z2 = (const float2*)(fsl + ((size_t)(it * 32 + li) * N_ + nt * 8 + ln) * D_);
        float2 za = z2[0], zb = z2[1], zc = z2[2];
        float z0 = za.x, z1 = za.y, z2v = zb.x, z3 = zb.y, z4 = zc.x, z5 = zc.y;
        float s0 = z0, s1 = z1, s2 = z2v, s3 = z3, s4 = z4, s5 = z5;
#define CSWP(a, b) { float _mx = fmaxf(a, b); float _mn = fminf(a, b); a = _mx; b = _mn; }
        CSWP(s1, s2) CSWP(s4, s5) CSWP(s0, s2) CSWP(s3, s5)
        CSWP(s0, s1) CSWP(s3, s4) CSWP(s2, s5) CSWP(s0, s3)
        CSWP(s1, s4) CSWP(s2, s4) CSWP(s1, s3) CSWP(s2, s3)
#undef CSWP
        float cs = s0; int k = 1; float ts = cs;
        cs += s1; if (1.0f + 2.0f * s1 > cs) { k = 2; ts = cs; }
        cs += s2; if (1.0f + 3.0f * s2 > cs) { k = 3; ts = cs; }
        cs += s3; if (1.0f + 4.0f * s3 > cs) { k = 4; ts = cs; }
        cs += s4; if (1.0f + 5.0f * s4 > cs) { k = 5; ts = cs; }
        cs += s5; if (1.0f + 6.0f * s5 > cs) { k = 6; ts = cs; }
        float tau = (ts - 1.0f) / (float)k;

        fsm[ln * 6 + 0][li] = fmaxf(z0 - tau, 0.0f);
        fsm[ln * 6 + 1][li] = fmaxf(z1 - tau, 0.0f);
        fsm[ln * 6 + 2][li] = fmaxf(z2v - tau, 0.0f);
        fsm[ln * 6 + 3][li] = fmaxf(z3 - tau, 0.0f);
        fsm[ln * 6 + 4][li] = fmaxf(z4 - tau, 0.0f);
        fsm[ln * 6 + 5][li] = fmaxf(z5 - tau, 0.0f);
    }

    // ---- resp -> tf32 pair-interleaved, gather form ----
    {
        int fi = gt * 4;              // output word base (4 words)
        int nu = fi >> 6;
        int cc = (fi & 63) >> 2;      // 0..15
        int s = cc >> 1, half = cc & 1;
        const float* r = resp + (size_t)nu * 64 + 8 * s + 2 * half;
        float2 ra = *(const float2*)(r);       // src c +0, +1
        float2 rb = *(const float2*)(r + 4);   // src c +4, +5
        uint4 o;
        o.x = tf32r(ra.x);   // col' +0 <- c+0
        o.y = tf32r(rb.x);   // col' +1 <- c+4
        o.z = tf32r(ra.y);   // col' +2 <- c+1
        o.w = tf32r(rb.y);   // col' +3 <- c+5
        *(uint4*)(g_respP + fi) = o;
    }

    if (gt < (B_ * I_) / 4) {   // x split
        float4 v = ((const float4*)x)[gt];
        float f[4] = { v.x, v.y, v.z, v.w };
        __nv_bfloat16 h[4], l[4];
#pragma unroll
        for (int i = 0; i < 4; i++) {
            h[i] = __float2bfloat16_rn(f[i]);
            l[i] = __float2bfloat16_rn(f[i] - __bfloat162float(h[i]));
        }
        __nv_bfloat162 h01(h[0], h[1]), h23(h[2], h[3]);
        __nv_bfloat162 l01(l[0], l[1]), l23(l[2], l[3]);
        uint2 uh = make_uint2(*reinterpret_cast<uint32_t*>(&h01),
                              *reinterpret_cast<uint32_t*>(&h23));
        uint2 ul = make_uint2(*reinterpret_cast<uint32_t*>(&l01),
                              *reinterpret_cast<uint32_t*>(&l23));
        *(uint2*)(g_xh + (size_t)gt * 4) = uh;
        *(uint2*)(g_xl + (size_t)gt * 4) = ul;
    }

    if (gt < ND_) {   // scale/offset
        float s = 0.5f * expf(-lt[gt]);
        g_sc[gt] = s;
        g_of[gt] = 0.5f - th[gt] * s;
    }

    // ---- emit transposed bf16 W: rows m = nt*48 + r, cols k = it*32 + lane ----
    __syncthreads();
    {
        int w = t >> 5, lane = t & 31;
#pragma unroll
        for (int r2 = 0; r2 < 6; r2++) {
            int r = w * 6 + r2;
            float v = fsm[r][lane];
            __nv_bfloat16 hi = __float2bfloat16_rn(v);
            __nv_bfloat16 lo = __float2bfloat16_rn(v - __bfloat162float(hi));
            size_t o = (size_t)(nt * 48 + r) * I_ + it * 32 + lane;
            g_Wh[o] = hi;
            g_Wl[o] = lo;
        }
    }
}

// ---------------------------------------------------------------------------
// Kernel B: tensor GEMM (unchanged from R12)
// ---------------------------------------------------------------------------
__global__ void __launch_bounds__(256) k_gemm() {
    __shared__ __nv_bfloat16 Wh_s[128][72], Wl_s[128][72];
    __shared__ __nv_bfloat16 Xh_s[64][72],  Xl_s[64][72];

    int t    = threadIdx.x;
    int w    = t >> 5;
    int lane = t & 31;
    int g    = lane >> 2;
    int tig  = lane & 3;
    int jt   = blockIdx.x;
    int mt   = blockIdx.y;

    float acc[8][4];
#pragma unroll
    for (int jf = 0; jf < 8; jf++)
#pragma unroll
        for (int i = 0; i < 4; i++) acc[jf][i] = 0.0f;

    for (int kc = 0; kc < I_; kc += 64) {
        __syncthreads();
        {
#pragma unroll
            for (int i = 0; i < 4; i++) {
                int idx = t + i * 256;
                int row = idx >> 3, seg = idx & 7;
                size_t go = (size_t)(mt * 128 + row) * I_ + kc + seg * 8;
                *(uint4*)&Wh_s[row][seg * 8] = *(const uint4*)(g_Wh + go);
                *(uint4*)&Wl_s[row][seg * 8] = *(const uint4*)(g_Wl + go);
            }
#pragma unroll
            for (int i = 0; i < 2; i++) {
                int idx = t + i * 256;
                int row = idx >> 3, seg = idx & 7;
                size_t go = (size_t)(jt * 64 + row) * I_ + kc + seg * 8;
                *(uint4*)&Xh_s[row][seg * 8] = *(const uint4*)(g_xh + go);
                *(uint4*)&Xl_s[row][seg * 8] = *(const uint4*)(g_xl + go);
            }
        }
        __syncthreads();

#pragma unroll
        for (int kst = 0; kst < 4; kst++) {
            int k0 = kst * 16 + 2 * tig;
            uint32_t ah0 = *(uint32_t*)&Wh_s[w * 16 + g][k0];
            uint32_t ah1 = *(uint32_t*)&Wh_s[w * 16 + g + 8][k0];
            uint32_t ah2 = *(uint32_t*)&Wh_s[w * 16 + g][k0 + 8];
            uint32_t ah3 = *(uint32_t*)&Wh_s[w * 16 + g + 8][k0 + 8];
            uint32_t al0 = *(uint32_t*)&Wl_s[w * 16 + g][k0];
            uint32_t al1 = *(uint32_t*)&Wl_s[w * 16 + g + 8][k0];
            uint32_t al2 = *(uint32_t*)&Wl_s[w * 16 + g][k0 + 8];
            uint32_t al3 = *(uint32_t*)&Wl_s[w * 16 + g + 8][k0 + 8];

#pragma unroll
            for (int jf = 0; jf < 8; jf++) {
                uint32_t bh0 = *(uint32_t*)&Xh_s[jf * 8 + g][k0];
                uint32_t bh1 = *(uint32_t*)&Xh_s[jf * 8 + g][k0 + 8];
                uint32_t bl0 = *(uint32_t*)&Xl_s[jf * 8 + g][k0];
                uint32_t bl1 = *(uint32_t*)&Xl_s[jf * 8 + g][k0 + 8];
                mma_bf16(acc[jf], ah0, ah1, ah2, ah3, bh0, bh1);
                mma_bf16(acc[jf], al0, al1, al2, al3, bh0, bh1);
                mma_bf16(acc[jf], ah0, ah1, ah2, ah3, bl0, bl1);
            }
        }
    }

    int m0 = mt * 128 + w * 16;
#pragma unroll
    for (int jf = 0; jf < 8; jf++) {
        int j = jt * 64 + jf * 8 + 2 * tig;
        *(float2*)&g_FVt[(size_t)(m0 + g) * B_ + j]     = make_float2(acc[jf][0], acc[jf][1]);
        *(float2*)&g_FVt[(size_t)(m0 + g + 8) * B_ + j] = make_float2(acc[jf][2], acc[jf][3]);
    }
}

// ---------------------------------------------------------------------------
// Kernel C (tensor forest, unchanged from R12): pipelined FVt loads.
// ---------------------------------------------------------------------------
__global__ void __launch_bounds__(256) k_forest(float* __restrict__ out) {
    __shared__ uint32_t resp_s[8][U_][72];
    __shared__ float sc_s[48], of_s[48];

    int t    = threadIdx.x;
    int w    = t >> 5;
    int lane = t & 31;
    int g    = lane >> 2;
    int tig  = lane & 3;
    int bt   = blockIdx.x;   // 8 b-tiles of 128
    int ng   = blockIdx.y;   // 64 n-groups of 8

    if (t < 48) { sc_s[t] = g_sc[ng * 48 + t]; of_s[t] = g_of[ng * 48 + t]; }

    {   // stage 8 response tiles
        const uint4* src = (const uint4*)(g_respP + (size_t)ng * 8 * (U_ * L_));
#pragma unroll
        for (int j = 0; j < 8; j++) {
            int idx = t + j * 256;
            uint4 v = src[idx];
            int fi = idx * 4;
            int row = fi >> 6, col = fi & 63;
            *(uint4*)&resp_s[row >> 4][row & 15][col] = v;
        }
    }

    float acc[2][4] = {};
    int b_r0 = bt * 128 + w * 16 + g;
    const float* fvb = g_FVt + (size_t)ng * 48 * B_;

    float fv[2][12];
#pragma unroll
    for (int d = 0; d < 6; d++) {
        fv[0][d]     = fvb[(size_t)d * B_ + b_r0];
        fv[0][6 + d] = fvb[(size_t)d * B_ + b_r0 + 8];
    }

    __syncthreads();

#pragma unroll
    for (int nl = 0; nl < 8; nl++) {
        int cur = nl & 1, nxt = cur ^ 1;

        if (nl < 7) {
            const float* fvn = fvb + (size_t)(nl + 1) * 6 * B_;
#pragma unroll
            for (int d = 0; d < 6; d++) {
                fv[nxt][d]     = fvn[(size_t)d * B_ + b_r0];
                fv[nxt][6 + d] = fvn[(size_t)d * B_ + b_r0 + 8];
            }
        }

        float h0[6], h1[6];
#pragma unroll
        for (int d = 0; d < 6; d++) {
            float sc = sc_s[nl * 6 + d], of = of_s[nl * 6 + d];
            h0[d] = fminf(fmaxf(fv[cur][d]     * sc + of, 0.0f), 1.0f);
            h1[d] = fminf(fmaxf(fv[cur][6 + d] * sc + of, 0.0f), 1.0f);
        }

        float f0a = (tig & 1) ? (1.0f - h0[0]) : h0[0];
        float f0b = (tig & 1) ? (1.0f - h1[0]) : h1[0];
        float f1a = (tig & 2) ? (1.0f - h0[1]) : h0[1];
        float f1b = (tig & 2) ? (1.0f - h1[1]) : h1[1];
        float F0 = f0a * f1a, F1 = f0b * f1b;
        float A00 = F0 * h0[2], A01 = F0 * (1.0f - h0[2]);
        float A10 = F1 * h1[2], A11 = F1 * (1.0f - h1[2]);

        float S0[8], S1[8];
        {
            float p0 = h0[3], p1 = 1.0f - h0[3];
            float r0 = h0[4], r1 = 1.0f - h0[4];
            float q0 = p0 * r0, q1 = p1 * r0, q2 = p0 * r1, q3 = p1 * r1;
            float t5 = h0[5], u5 = 1.0f - h0[5];
            S0[0] = q0 * t5; S0[1] = q1 * t5; S0[2] = q2 * t5; S0[3] = q3 * t5;
            S0[4] = q0 * u5; S0[5] = q1 * u5; S0[6] = q2 * u5; S0[7] = q3 * u5;
        }
        {
            float p0 = h1[3], p1 = 1.0f - h1[3];
            float r0 = h1[4], r1 = 1.0f - h1[4];
            float q0 = p0 * r0, q1 = p1 * r0, q2 = p0 * r1, q3 = p1 * r1;
            float t5 = h1[5], u5 = 1.0f - h1[5];
            S1[0] = q0 * t5; S1[1] = q1 * t5; S1[2] = q2 * t5; S1[3] = q3 * t5;
            S1[4] = q0 * u5; S1[5] = q1 * u5; S1[6] = q2 * u5; S1[7] = q3 * u5;
        }

#pragma unroll
        for (int s = 0; s < 8; s++) {
            uint32_t a0 = __float_as_uint(A00 * S0[s]);
            uint32_t a1 = __float_as_uint(A10 * S1[s]);
            uint32_t a2 = __float_as_uint(A01 * S0[s]);
            uint32_t a3 = __float_as_uint(A11 * S1[s]);
#pragma unroll
            for (int nr = 0; nr < 2; nr++) {
                uint2 bb = *(const uint2*)&resp_s[nl][nr * 8 + g][8 * s + 2 * tig];
                mma_tf32(acc[nr], a0, a1, a2, a3, bb.x, bb.y);
            }
        }
    }

#pragma unroll
    for (int nr = 0; nr < 2; nr++) {
        int u = nr * 8 + 2 * tig;
        atomicAdd(&out[b_r0 * U_ + u],           acc[nr][0]);
        atomicAdd(&out[b_r0 * U_ + u + 1],       acc[nr][1]);
        atomicAdd(&out[(b_r0 + 8) * U_ + u],     acc[nr][2]);
        atomicAdd(&out[(b_r0 + 8) * U_ + u + 1], acc[nr][3]);
    }
}

// ---------------------------------------------------------------------------
extern "C" void kernel_launch(void* const* d_in, const int* in_sizes, int n_in,
                              void* d_out, int out_size) {
    const float* x    = (const float*)d_in[0];  // [B, I]
    const float* fsl  = (const float*)d_in[1];  // [I, N, D]
    const float* th   = (const float*)d_in[2];  // [N, D]
    const float* lt   = (const float*)d_in[3];  // [N, D]
    const float* resp = (const float*)d_in[4];  // [N, U, 2^D]
    float* out = (float*)d_out;                 // [B, U]

    cudaMemsetAsync(out, 0, (size_t)B_ * U_ * sizeof(float), 0);

    k_prep<<<512, 256>>>(fsl, x, th, lt, resp);
    k_gemm<<<dim3(B_ / 64, ND_ / 128), 256>>>();
    k_forest<<<dim3(B_ / 128, N_ / 8), 256>>>(out);
}